// round 2
// baseline (speedup 1.0000x reference)
#include <cuda_runtime.h>
#include <stdint.h>

// ---------------------------------------------------------------------------
// Shapes (fixed by the problem):
//   vit_feature : (B=16, D=256, R=1024)  float32
//   lag_feature : (B=16, S=20,  D=256)   float32
//   lag_vit_map : (B=16, S=20,  R=1024)  float32
// Outputs (concatenated, float32):
//   out1 vit_corr : (R, B, D)        = 4,194,304
//   out2 lag_corr : (R, B, 4, D)     = 16,777,216
//   out3 neg      : (R, B, 5, D)     = 20,971,520
// ---------------------------------------------------------------------------

#define B_ 16
#define D_ 256
#define R_ 1024
#define S_ 20
#define TOPK_ 4
#define NEGN_ 5

static __device__ int g_cols[B_ * R_ * TOPK_];

// ---------------- threefry-2x32, JAX partitionable 32-bit path --------------
// key = jax.random.key(1234) -> data (k1, k2) = (0, 1234)
// element i: (x0,x1) = threefry2x32((0,1234), (hi32(i)=0, lo32(i)=i)); bits = x0 ^ x1
__device__ __forceinline__ uint32_t rotl32(uint32_t x, int r) {
    return __funnelshift_l(x, x, r);
}

__device__ __forceinline__ uint32_t threefry_bits(uint32_t ctr_lo) {
    const uint32_t K0 = 0u;
    const uint32_t K1 = 1234u;
    const uint32_t K2 = 0x1BD11BDAu ^ K0 ^ K1;
    uint32_t ks[3] = {K0, K1, K2};
    uint32_t x0 = 0u + K0;
    uint32_t x1 = ctr_lo + K1;
    const int ROT0[4] = {13, 15, 26, 6};
    const int ROT1[4] = {17, 29, 16, 24};
#pragma unroll
    for (int i = 0; i < 5; ++i) {
#pragma unroll
        for (int j = 0; j < 4; ++j) {
            int r = (i & 1) ? ROT1[j] : ROT0[j];
            x0 += x1;
            x1 = rotl32(x1, r);
            x1 ^= x0;
        }
        x0 += ks[(i + 1) % 3];
        x1 += ks[(i + 2) % 3] + (uint32_t)(i + 1);
    }
    return x0 ^ x1;
}

__device__ __forceinline__ unsigned long long warp_max_ull(unsigned long long v) {
#pragma unroll
    for (int o = 16; o > 0; o >>= 1) {
        unsigned long long u = __shfl_xor_sync(0xffffffffu, v, o);
        v = (u > v) ? u : v;
    }
    return v;
}

// sorted-descending insert into 5 regs
#define INSERT5(k)                                          \
    do {                                                    \
        if ((k) > a4) {                                     \
            a4 = (k);                                       \
            unsigned long long _t;                          \
            if (a4 > a3) { _t = a3; a3 = a4; a4 = _t; }     \
            if (a3 > a2) { _t = a2; a2 = a3; a3 = _t; }     \
            if (a2 > a1) { _t = a1; a1 = a2; a2 = _t; }     \
            if (a1 > a0) { _t = a0; a0 = a1; a1 = _t; }     \
        }                                                   \
    } while (0)

// ---------------- Kernel 1: transpose vit_feature -> vit_corr ---------------
// out1[(r*16 + b)*256 + d] = vit[b*262144 + d*1024 + r]
__global__ void transpose_kernel(const float* __restrict__ vit,
                                 float* __restrict__ out1) {
    __shared__ float tile[32][33];
    int b = blockIdx.z;
    int r0 = blockIdx.x * 32;
    int d0 = blockIdx.y * 32;
    int tx = threadIdx.x, ty = threadIdx.y;  // block (32, 8)
    const float* src = vit + b * (D_ * R_);
#pragma unroll
    for (int k = 0; k < 4; ++k) {
        int d = d0 + ty + k * 8;
        tile[ty + k * 8][tx] = src[d * R_ + r0 + tx];
    }
    __syncthreads();
#pragma unroll
    for (int k = 0; k < 4; ++k) {
        int r = r0 + ty + k * 8;
        int d = d0 + tx;
        out1[(r * B_ + b) * D_ + d] = tile[tx][ty + k * 8];
    }
}

// ---------------- Kernel 2: top-4 over S of m[b,r,s]=lag_vit_map[b,s,r] -----
__global__ void cols_kernel(const float* __restrict__ lvm) {
    int t = blockIdx.x * blockDim.x + threadIdx.x;  // 0..16383
    if (t >= B_ * R_) return;
    int b = t >> 10;
    int r = t & (R_ - 1);
    const float* base = lvm + b * (S_ * R_) + r;
    unsigned long long a0 = 0, a1 = 0, a2 = 0, a3 = 0;
#pragma unroll
    for (int s = 0; s < S_; ++s) {
        uint32_t u = __float_as_uint(base[s * R_]);
        // monotone transform for signed floats (no NaN in inputs)
        uint32_t m = u ^ (uint32_t)(((int32_t)u >> 31) | 0x80000000u);
        unsigned long long k =
            ((unsigned long long)m << 32) | (uint32_t)(~(uint32_t)s);
        if (k > a3) {
            a3 = k;
            unsigned long long _t;
            if (a3 > a2) { _t = a2; a2 = a3; a3 = _t; }
            if (a2 > a1) { _t = a1; a1 = a2; a2 = _t; }
            if (a1 > a0) { _t = a0; a0 = a1; a1 = _t; }
        }
    }
    int o = t * TOPK_;
    g_cols[o + 0] = (int)(~(uint32_t)a0);
    g_cols[o + 1] = (int)(~(uint32_t)a1);
    g_cols[o + 2] = (int)(~(uint32_t)a2);
    g_cols[o + 3] = (int)(~(uint32_t)a3);
}

// ---------------- Kernel 3: fused RNG + top-5 + neg write -------------------
// One block per (r,b) row. scores[r,b,r2] = uniform(threefry(r*16384+b*1024+r2)),
// with scores[r, 15, r] = -1 (i.e. skip that candidate).
// neg[r,b,n,:] = vit_corr[idx_n, 15, :]  (read back from out1 region of d_out)
__global__ void __launch_bounds__(128)
neg_kernel(const float4* __restrict__ vitcorr4, float4* __restrict__ out3_4) {
    int rb = blockIdx.x;  // r*16 + b
    int r = rb >> 4;
    int b = rb & 15;
    int tid = threadIdx.x;

    unsigned long long a0 = 0, a1 = 0, a2 = 0, a3 = 0, a4 = 0;
#pragma unroll
    for (int it = 0; it < 8; ++it) {
        int r2 = tid + it * 128;
        uint32_t lin = (uint32_t)(rb * R_ + r2);  // r*16384 + b*1024 + r2
        uint32_t bits = threefry_bits(lin);
        // uniform value = bitcast((bits>>9)|0x3f800000) - 1 : monotone in bits>>9
        bool diag_excl = (b == (B_ - 1)) && (r2 == r);
        if (!diag_excl) {
            unsigned long long key =
                ((unsigned long long)(bits >> 9) << 32) |
                (uint32_t)(~(uint32_t)r2);
            INSERT5(key);
        }
    }

    // warp-level: pop warp max 5 times (keys are globally unique -> exactly
    // one lane matches each pop)
    __shared__ unsigned long long wkeys[4][5];
    __shared__ int sidx[5];
    int wid = tid >> 5;
#pragma unroll
    for (int j = 0; j < 5; ++j) {
        unsigned long long m = warp_max_ull(a0);
        if (a0 == m) { a0 = a1; a1 = a2; a2 = a3; a3 = a4; a4 = 0; }
        if ((tid & 31) == 0) wkeys[wid][j] = m;
    }
    __syncthreads();

    // block-level: warp 0 merges 20 candidates
    if (tid < 32) {
        unsigned long long k = 0;
        if (tid < 20) k = wkeys[tid / 5][tid % 5];
#pragma unroll
        for (int j = 0; j < 5; ++j) {
            unsigned long long m = warp_max_ull(k);
            if (k == m) k = 0;
            if (tid == 0) sidx[j] = (int)(~(uint32_t)m);
        }
    }
    __syncthreads();

    // write phase: 5 rows x 64 float4 (256 floats each)
#pragma unroll
    for (int t = tid; t < NEGN_ * (D_ / 4); t += 128) {
        int n = t >> 6;
        int f = t & 63;
        int idx = sidx[n];
        out3_4[(rb * NEGN_ + n) * (D_ / 4) + f] =
            vitcorr4[(idx * B_ + (B_ - 1)) * (D_ / 4) + f];
    }
}

// ---------------- Kernel 4: lag_corr gather-write ---------------------------
// out2[((r*16+b)*4+k)*256 + d] = lag_feature[(b*20 + cols[b,r,k])*256 + d]
__global__ void lag_kernel(const float4* __restrict__ lag4,
                           float4* __restrict__ out2_4) {
    int t = blockIdx.x * 256 + threadIdx.x;  // over 4,194,304 float4s
    int rid = t >> 6;        // (r*16+b)*4+k
    int f = t & 63;
    int k = rid & 3;
    int b = (rid >> 2) & 15;
    int r = rid >> 6;
    int col = g_cols[((b << 10) + r) * TOPK_ + k];
    out2_4[t] = lag4[(b * S_ + col) * (D_ / 4) + f];
}

// ---------------------------------------------------------------------------
extern "C" void kernel_launch(void* const* d_in, const int* in_sizes, int n_in,
                              void* d_out, int out_size) {
    const float* vit = (const float*)d_in[0];
    const float* lag = (const float*)d_in[1];
    const float* lvm = (const float*)d_in[2];
    float* out = (float*)d_out;

    float* out1 = out;                                  // 4,194,304
    float* out2 = out + (size_t)R_ * B_ * D_;           // +16,777,216
    float* out3 = out2 + (size_t)R_ * B_ * TOPK_ * D_;  // +20,971,520

    // 1) transpose (writes out1; keeps vit[15] rows L2-hot for neg gather)
    {
        dim3 tb(32, 8);
        dim3 tg(R_ / 32, D_ / 32, B_);
        transpose_kernel<<<tg, tb>>>(vit, out1);
    }
    // 2) top-4 cols (tiny)
    cols_kernel<<<(B_ * R_) / 256, 256>>>(lvm);
    // 3) fused RNG + top-5 + neg write (dominant; overlaps 84MB write w/ ALU)
    neg_kernel<<<R_ * B_, 128>>>((const float4*)out1, (float4*)out3);
    // 4) lag_corr gather-write
    lag_kernel<<<(R_ * B_ * TOPK_ * (D_ / 4)) / 256, 256>>>(
        (const float4*)lag, (float4*)out2);
}

// round 6
// speedup vs baseline: 1.3060x; 1.3060x over previous
#include <cuda_runtime.h>
#include <stdint.h>

// ---------------------------------------------------------------------------
//   vit_feature : (B=16, D=256, R=1024)  f32
//   lag_feature : (B=16, S=20,  D=256)   f32
//   lag_vit_map : (B=16, S=20,  R=1024)  f32
// out (concat f32): vit_corr (R,B,D) | lag_corr (R,B,4,D) | neg (R,B,5,D)
// ---------------------------------------------------------------------------

#define B_ 16
#define D_ 256
#define R_ 1024
#define S_ 20
#define TOPK_ 4
#define NEGN_ 5

static __device__ int   g_cols[B_ * R_ * TOPK_];
static __device__ float g_vit15[R_ * D_];   // vit[b=15] transposed: [r][d]

// ---------------- threefry-2x32, JAX partitionable 32-bit path --------------
__device__ __forceinline__ uint32_t rotl32(uint32_t x, int r) {
    return __funnelshift_l(x, x, r);
}

__device__ __forceinline__ uint32_t threefry_bits(uint32_t ctr_lo) {
    const uint32_t K0 = 0u;
    const uint32_t K1 = 1234u;
    const uint32_t K2 = 0x1BD11BDAu ^ K0 ^ K1;
    uint32_t ks[3] = {K0, K1, K2};
    uint32_t x0 = 0u + K0;
    uint32_t x1 = ctr_lo + K1;
    const int ROT0[4] = {13, 15, 26, 6};
    const int ROT1[4] = {17, 29, 16, 24};
#pragma unroll
    for (int i = 0; i < 5; ++i) {
#pragma unroll
        for (int j = 0; j < 4; ++j) {
            int r = (i & 1) ? ROT1[j] : ROT0[j];
            x0 += x1;
            x1 = rotl32(x1, r);
            x1 ^= x0;
        }
        x0 += ks[(i + 1) % 3];
        x1 += ks[(i + 2) % 3] + (uint32_t)(i + 1);
    }
    return x0 ^ x1;
}

__device__ __forceinline__ unsigned long long warp_max_ull(unsigned long long v) {
#pragma unroll
    for (int o = 16; o > 0; o >>= 1) {
        unsigned long long u = __shfl_xor_sync(0xffffffffu, v, o);
        v = (u > v) ? u : v;
    }
    return v;
}

#define INSERT5(k)                                          \
    do {                                                    \
        if ((k) > a4) {                                     \
            a4 = (k);                                       \
            unsigned long long _t;                          \
            if (a4 > a3) { _t = a3; a3 = a4; a4 = _t; }     \
            if (a3 > a2) { _t = a2; a2 = a3; a3 = _t; }     \
            if (a2 > a1) { _t = a1; a1 = a2; a2 = _t; }     \
            if (a1 > a0) { _t = a0; a0 = a1; a1 = _t; }     \
        }                                                   \
    } while (0)

// ---------------- Stage 1: vit[15] mini-transpose + top-4 cols --------------
// blocks [0,256): transpose vit[15] (32x32 tiles) into g_vit15
// blocks [256,384): top-4 over S of lag_vit_map[b, :, r]
__global__ void __launch_bounds__(128) stage1_kernel(
    const float* __restrict__ vit, const float* __restrict__ lvm) {
    int bid = blockIdx.x;
    int tid = threadIdx.x;
    if (bid < 256) {
        __shared__ float tile[32][33];
        int r0 = (bid & 31) * 32;
        int d0 = (bid >> 5) * 32;
        int tx = tid & 31, ty = tid >> 5;
        const float* src = vit + 15 * (D_ * R_);
#pragma unroll
        for (int k = 0; k < 8; ++k) {
            int dl = k * 4 + ty;
            tile[dl][tx] = src[(d0 + dl) * R_ + r0 + tx];
        }
        __syncthreads();
#pragma unroll
        for (int k = 0; k < 8; ++k) {
            int rl = k * 4 + ty;
            g_vit15[(r0 + rl) * D_ + d0 + tx] = tile[tx][rl];
        }
    } else {
        int t = (bid - 256) * 128 + tid;  // 0..16383
        int b = t >> 10;
        int r = t & (R_ - 1);
        const float* base = lvm + b * (S_ * R_) + r;
        unsigned long long a0 = 0, a1 = 0, a2 = 0, a3 = 0;
#pragma unroll
        for (int s = 0; s < S_; ++s) {
            uint32_t u = __float_as_uint(base[s * R_]);
            uint32_t m = u ^ (uint32_t)(((int32_t)u >> 31) | 0x80000000u);
            unsigned long long k =
                ((unsigned long long)m << 32) | (uint32_t)(~(uint32_t)s);
            if (k > a3) {
                a3 = k;
                unsigned long long _t;
                if (a3 > a2) { _t = a2; a2 = a3; a3 = _t; }
                if (a2 > a1) { _t = a1; a1 = a2; a2 = _t; }
                if (a1 > a0) { _t = a0; a0 = a1; a1 = _t; }
            }
        }
        int o = t * TOPK_;
        g_cols[o + 0] = (int)(~(uint32_t)a0);
        g_cols[o + 1] = (int)(~(uint32_t)a1);
        g_cols[o + 2] = (int)(~(uint32_t)a2);
        g_cols[o + 3] = (int)(~(uint32_t)a3);
    }
}

// ---------------- Stage 2: fat fused kernel ---------------------------------
// Role-interleaved blocks so ALU-bound (neg/RNG) and memory-bound
// (transpose/lag) work co-resides on every SM in every wave.
//   bid%7 in {0..3} -> neg row   (16384 blocks total)
//   bid%7 == 4      -> transpose tile (4096 blocks)
//   bid%7 in {5,6}  -> lag slab  (8192 blocks)
#define FAT_GRID (4096 * 7)
#define THRESH_ 0xFC000000u  // top 1/64: E[survivors/row]=16, P(<5)~4e-4

__global__ void __launch_bounds__(128) fat_kernel(
    const float* __restrict__ vit, const float4* __restrict__ lag4,
    float* __restrict__ out1, float4* __restrict__ out2_4,
    float4* __restrict__ out3_4) {
    int bid = blockIdx.x;
    int tid = threadIdx.x;
    int grp = bid / 7;
    int lane7 = bid - grp * 7;

    if (lane7 < 4) {
        // ---------------- neg role: one (r,b) row ----------------
        int rb = grp * 4 + lane7;
        int r = rb >> 4;
        int b = rb & 15;

        __shared__ unsigned long long wkeys[4][5];
        __shared__ int sidx[5];
        __shared__ int scnt[4];

        unsigned long long a0 = 0, a1 = 0, a2 = 0, a3 = 0, a4 = 0;
        int cnt = 0;
        bool isb15 = (b == (B_ - 1));
#pragma unroll
        for (int it = 0; it < 8; ++it) {
            int r2 = tid + it * 128;
            uint32_t bits = threefry_bits((uint32_t)(rb * R_ + r2));
            bool ok = (bits >= THRESH_) && !(isb15 && (r2 == r));
            if (ok) {
                ++cnt;
                unsigned long long key =
                    ((unsigned long long)(bits >> 9) << 32) |
                    (uint32_t)(~(uint32_t)r2);
                INSERT5(key);
            }
        }
        // block-wide survivor count (exact-fallback guard)
#pragma unroll
        for (int o = 16; o > 0; o >>= 1) cnt += __shfl_xor_sync(0xffffffffu, cnt, o);
        int wid = tid >> 5;
        if ((tid & 31) == 0) scnt[wid] = cnt;
        __syncthreads();
        int total = scnt[0] + scnt[1] + scnt[2] + scnt[3];
        if (total < NEGN_) {  // astronomically rare; exact rescan
            a0 = a1 = a2 = a3 = a4 = 0;
#pragma unroll
            for (int it = 0; it < 8; ++it) {
                int r2 = tid + it * 128;
                uint32_t bits = threefry_bits((uint32_t)(rb * R_ + r2));
                if (!(isb15 && (r2 == r))) {
                    unsigned long long key =
                        ((unsigned long long)(bits >> 9) << 32) |
                        (uint32_t)(~(uint32_t)r2);
                    INSERT5(key);
                }
            }
        }
        // warp-level: pop warp max 5 times (nonzero keys globally unique)
#pragma unroll
        for (int j = 0; j < NEGN_; ++j) {
            unsigned long long m = warp_max_ull(a0);
            if (a0 == m) { a0 = a1; a1 = a2; a2 = a3; a3 = a4; a4 = 0; }
            if ((tid & 31) == 0) wkeys[wid][j] = m;
        }
        __syncthreads();
        if (tid < 32) {
            unsigned long long k = 0;
            if (tid < 20) k = wkeys[tid / 5][tid % 5];
#pragma unroll
            for (int j = 0; j < NEGN_; ++j) {
                unsigned long long m = warp_max_ull(k);
                if (k == m) k = 0;
                if (tid == 0) sidx[j] = (int)(~(uint32_t)m);
            }
        }
        __syncthreads();
        const float4* v15 = (const float4*)g_vit15;
        for (int t = tid; t < NEGN_ * (D_ / 4); t += 128) {
            int n = t >> 6;
            int f = t & 63;
            out3_4[(rb * NEGN_ + n) * (D_ / 4) + f] = v15[sidx[n] * 64 + f];
        }
    } else if (lane7 == 4) {
        // ---------------- transpose role: one 32x32 tile ----------------
        // grp in 0..4095 = b(16) x rt(32) x dt(8)
        __shared__ float tile[32][33];
        int b = grp >> 8;
        int rem = grp & 255;
        int r0 = (rem & 31) * 32;
        int d0 = (rem >> 5) * 32;
        int tx = tid & 31, ty = tid >> 5;
        const float* src = vit + b * (D_ * R_);
#pragma unroll
        for (int k = 0; k < 8; ++k) {
            int dl = k * 4 + ty;
            tile[dl][tx] = src[(d0 + dl) * R_ + r0 + tx];
        }
        __syncthreads();
#pragma unroll
        for (int k = 0; k < 8; ++k) {
            int rl = k * 4 + ty;
            out1[((r0 + rl) * B_ + b) * D_ + d0 + tx] = tile[tx][rl];
        }
    } else {
        // ---------------- lag role: 512 consecutive float4 of out2 ------
        int li = grp * 2 + (lane7 - 5);  // 0..8191
        int base = li * 512;
#pragma unroll
        for (int j = 0; j < 4; ++j) {
            int t = base + j * 128 + tid;
            int rid = t >> 6;  // (r*16+b)*4+k
            int f = t & 63;
            int k = rid & 3;
            int b = (rid >> 2) & 15;
            int r = rid >> 6;
            int col = g_cols[(((b << 10) + r) << 2) + k];
            out2_4[t] = lag4[(b * S_ + col) * (D_ / 4) + f];
        }
    }
}

// ---------------------------------------------------------------------------
extern "C" void kernel_launch(void* const* d_in, const int* in_sizes, int n_in,
                              void* d_out, int out_size) {
    const float* vit = (const float*)d_in[0];
    const float* lag = (const float*)d_in[1];
    const float* lvm = (const float*)d_in[2];
    float* out = (float*)d_out;

    float* out1 = out;                                  // R*B*D
    float* out2 = out1 + (size_t)R_ * B_ * D_;          // R*B*4*D
    float* out3 = out2 + (size_t)R_ * B_ * TOPK_ * D_;  // R*B*5*D

    stage1_kernel<<<384, 128>>>(vit, lvm);
    fat_kernel<<<FAT_GRID, 128>>>(vit, (const float4*)lag, out1,
                                  (float4*)out2, (float4*)out3);
}